// round 9
// baseline (speedup 1.0000x reference)
#include <cuda_runtime.h>
#include <math.h>

#define Nn   20000
#define Bb   128
#define Ee   320000
#define FIN  768
#define RAWF 5000
#define Hh   256
#define Cc   4
#define CH   100   // nodes per pooling chunk

// ---------------- scratch (static device globals; no allocation) ----------------
__device__ int      g_indeg1[Nn], g_indeg2[Nn];
__device__ int      g_off1[Nn + 1];
__device__ int      g_cur1[Nn];
__device__ int      g_src1[Ee];
__device__ float    g_dinv1[Nn], g_dinv2[Nn];
__device__ int      g_cnt[Bb];
__device__ float    g_Hbuf[(size_t)Nn * Hh];
__device__ float    g_Xbuf[(size_t)Nn * Hh];
__device__ float    g_Pbuf[(size_t)Nn * Hh];    // scatter accumulation buffer
__device__ float    g_msum[Bb * RAWF];          // raw-feature segment sums
__device__ float    g_nx1[Bb * 512];
__device__ float    g_nx2[Bb * Hh];
__device__ float    g_acc0[Bb * Hh], g_acc1[Bb * Hh], g_acc2[Bb * Hh]; // mean-pool sums
__device__ unsigned g_maxacc[Bb * Hh];          // max-pool (uint-reinterpreted floats >= 0)
__device__ float    g_cat5[Bb * 5 * Hh];

// ---------------- setup kernels ----------------
__global__ void k_zero() {
    int i = blockIdx.x * blockDim.x + threadIdx.x;
    if (i < Nn) { g_indeg1[i] = 0; g_indeg2[i] = 0; g_cur1[i] = 0; }
    if (i < Bb) g_cnt[i] = 0;
    if (i < Bb * RAWF) g_msum[i] = 0.f;
    if (i < Bb * Hh) { g_acc0[i] = 0.f; g_acc1[i] = 0.f; g_acc2[i] = 0.f; g_maxacc[i] = 0u; }
}

__global__ void k_zeroP() {
    size_t i = (size_t)blockIdx.x * blockDim.x + threadIdx.x;
    if (i < (size_t)Nn * Hh) g_Pbuf[i] = 0.f;
}

__global__ void k_deg(const int* __restrict__ ei, const int* __restrict__ rei) {
    int e = blockIdx.x * blockDim.x + threadIdx.x;
    if (e < Ee) {
        atomicAdd(&g_indeg1[ei[Ee + e]], 1);
        atomicAdd(&g_indeg2[rei[Ee + e]], 1);
    }
}

__global__ void k_dinv() {
    int i = blockIdx.x * blockDim.x + threadIdx.x;
    if (i < Nn) {
        g_dinv1[i] = rsqrtf((float)g_indeg1[i] + 1.0f);
        g_dinv2[i] = rsqrtf((float)g_indeg2[i] + 1.0f);
    }
}

__global__ void k_cnt_hist(const int* __restrict__ batch) {
    int i = blockIdx.x * blockDim.x + threadIdx.x;
    if (i < Nn) atomicAdd(&g_cnt[batch[i]], 1);
}

__global__ void k_scan1() {
    __shared__ int ssum[1024];
    int t = threadIdx.x;
    const int n = Nn;
    int per = (n + 1023) / 1024;
    int s = 0;
    for (int i = 0; i < per; i++) { int idx = t * per + i; if (idx < n) s += g_indeg1[idx]; }
    ssum[t] = s; __syncthreads();
    for (int d = 1; d < 1024; d <<= 1) {
        int v = (t >= d) ? ssum[t - d] : 0; __syncthreads();
        ssum[t] += v; __syncthreads();
    }
    int base = (t == 0) ? 0 : ssum[t - 1];
    for (int i = 0; i < per; i++) { int idx = t * per + i; if (idx < n) { g_off1[idx] = base; base += g_indeg1[idx]; } }
    if (t == 1023) g_off1[n] = ssum[1023];
}

__global__ void k_fill1(const int* __restrict__ ei) {
    int e = blockIdx.x * blockDim.x + threadIdx.x;
    if (e < Ee) {
        int s = ei[e], d = ei[Ee + e];
        int p = g_off1[d] + atomicAdd(&g_cur1[d], 1);
        g_src1[p] = s;
    }
}

// ---------------- big SGEMM body: C = A[M,Kd] @ B[Kd,Nd], Nd=256 ----------------
__device__ __forceinline__ void sgemm_body(const float* __restrict__ A,
                                           const float* __restrict__ Bm,
                                           float* __restrict__ Cm, int M, int Kd, int Nd) {
    __shared__ float As[8][128];
    __shared__ float Bs[8][128];
    int tid = threadIdx.x;
    int m0 = blockIdx.x * 128, n0 = blockIdx.y * 128;
    int tx = tid & 15, ty = tid >> 4;
    float acc[8][8];
#pragma unroll
    for (int i = 0; i < 8; i++)
#pragma unroll
        for (int j = 0; j < 8; j++) acc[i][j] = 0.f;
    int ar = tid >> 1, ak = (tid & 1) * 4;
    int bk = tid >> 5, bn = (tid & 31) * 4;
    for (int k0 = 0; k0 < Kd; k0 += 8) {
        float4 av;
        int row = m0 + ar;
        if (row < M) av = *(const float4*)(A + (size_t)row * Kd + k0 + ak);
        else av = make_float4(0.f, 0.f, 0.f, 0.f);
        As[ak + 0][ar] = av.x; As[ak + 1][ar] = av.y;
        As[ak + 2][ar] = av.z; As[ak + 3][ar] = av.w;
        float4 bv = *(const float4*)(Bm + (size_t)(k0 + bk) * Nd + n0 + bn);
        *(float4*)&Bs[bk][bn] = bv;
        __syncthreads();
#pragma unroll
        for (int kk = 0; kk < 8; kk++) {
            float a[8], b[8];
            *(float4*)&a[0] = *(float4*)&As[kk][ty * 8];
            *(float4*)&a[4] = *(float4*)&As[kk][ty * 8 + 4];
            *(float4*)&b[0] = *(float4*)&Bs[kk][tx * 8];
            *(float4*)&b[4] = *(float4*)&Bs[kk][tx * 8 + 4];
#pragma unroll
            for (int i = 0; i < 8; i++)
#pragma unroll
                for (int j = 0; j < 8; j++) acc[i][j] += a[i] * b[j];
        }
        __syncthreads();
    }
#pragma unroll
    for (int i = 0; i < 8; i++) {
        int row = m0 + ty * 8 + i;
        if (row < M) {
            float* cp = Cm + (size_t)row * Nd + n0 + tx * 8;
            *(float4*)cp       = make_float4(acc[i][0], acc[i][1], acc[i][2], acc[i][3]);
            *(float4*)(cp + 4) = make_float4(acc[i][4], acc[i][5], acc[i][6], acc[i][7]);
        }
    }
}
__global__ void sgemm_g1(const float* __restrict__ A, const float* __restrict__ W) {
    sgemm_body(A, W, g_Hbuf, Nn, FIN, Hh);
}
__global__ void sgemm_dx(const float* __restrict__ A, const float* __restrict__ W) {
    sgemm_body(A, W, g_Hbuf, Nn, RAWF, Hh);
}
__global__ void sgemm_x(const float* __restrict__ W) {
    sgemm_body(g_Xbuf, W, g_Hbuf, Nn, Hh, Hh);
}

// ---------------- branch-1 GCN propagate (CSR gather, exonerated path) ----------
__global__ void gather1(const float* __restrict__ bias) {
    int i = blockIdx.x, f = threadIdx.x;
    float di = g_dinv1[i];
    float acc = di * di * g_Hbuf[(size_t)i * Hh + f];
    int e0 = g_off1[i], e1 = g_off1[i + 1];
    for (int e = e0; e < e1; e++) {
        int s = g_src1[e];
        acc += di * g_dinv1[s] * g_Hbuf[(size_t)s * Hh + f];
    }
    acc += bias[f];
    g_Xbuf[(size_t)i * Hh + f] = fmaxf(acc, 0.f);
}

// ---------------- branch-3 GCN propagate: direct edge-parallel scatter ----------
__global__ void k_scatter(const int* __restrict__ rei) {
    int e = blockIdx.x;
    int s = rei[e], d = rei[Ee + e];
    float w = g_dinv2[s] * g_dinv2[d];
    int f = threadIdx.x;
    atomicAdd(&g_Pbuf[(size_t)d * Hh + f], w * g_Hbuf[(size_t)s * Hh + f]);
}

__global__ void k_selfrelu(const float* __restrict__ bias) {
    int i = blockIdx.x, f = threadIdx.x;
    float di = g_dinv2[i];
    float acc = g_Pbuf[(size_t)i * Hh + f] + di * di * g_Hbuf[(size_t)i * Hh + f] + bias[f];
    g_Xbuf[(size_t)i * Hh + f] = fmaxf(acc, 0.f);
}

// ---------------- pooling: batch-driven atomic segment reductions ----------------
__global__ void pacc_mean(int which, const int* __restrict__ batch) {
    float* dst = (which == 0) ? g_acc0 : (which == 1) ? g_acc1 : g_acc2;
    int f = threadIdx.x;
    int i0 = blockIdx.x * CH;
    int i1 = min(i0 + CH, Nn);
    if (i0 >= Nn) return;
    int cur = batch[i0];
    float acc = 0.f;
    for (int i = i0; i < i1; i++) {
        int b = batch[i];
        if (b != cur) { atomicAdd(&dst[cur * Hh + f], acc); acc = 0.f; cur = b; }
        acc += g_Xbuf[(size_t)i * Hh + f];
    }
    atomicAdd(&dst[cur * Hh + f], acc);
}

__global__ void pacc_max(const int* __restrict__ batch) {
    int f = threadIdx.x;
    int i0 = blockIdx.x * CH;
    int i1 = min(i0 + CH, Nn);
    if (i0 >= Nn) return;
    int cur = batch[i0];
    float m = 0.f;
    for (int i = i0; i < i1; i++) {
        int b = batch[i];
        if (b != cur) { atomicMax(&g_maxacc[cur * Hh + f], __float_as_uint(m)); m = 0.f; cur = b; }
        m = fmaxf(m, g_Xbuf[(size_t)i * Hh + f]);
    }
    atomicMax(&g_maxacc[cur * Hh + f], __float_as_uint(m));
}

// Raw-feature segment sums (5000 features) into g_msum.
__global__ void k_msum(const float* __restrict__ dx, const int* __restrict__ batch) {
    int f = blockIdx.y * 256 + threadIdx.x;
    if (f >= RAWF) return;
    int i0 = blockIdx.x * CH;
    int i1 = min(i0 + CH, Nn);
    if (i0 >= Nn) return;
    int cur = batch[i0];
    float acc = 0.f;
    for (int i = i0; i < i1; i++) {
        int b = batch[i];
        if (b != cur) { atomicAdd(&g_msum[cur * RAWF + f], acc); acc = 0.f; cur = b; }
        acc += dx[(size_t)i * RAWF + f];
    }
    atomicAdd(&g_msum[cur * RAWF + f], acc);
}

// ---------------- branch-2 MLP: naive one-thread-per-output GEMMs ----------------
// Layer 1: nx1[r][c] = prelu( sum_k mean[r][k]*Wl1[k][c] + sum_k dx[root[r]][k]*Wl1[5000+k][c] + bl1[c] )
__global__ void k_mlp1(const float* __restrict__ dx, const int* __restrict__ root,
                       const float* __restrict__ Wl1, const float* __restrict__ bl1,
                       const float* __restrict__ pa) {
    int r = blockIdx.x;       // 0..127
    int c = threadIdx.x;      // 0..511
    float inv = 1.f / fmaxf((float)g_cnt[r], 1.f);
    const float* mrow = &g_msum[r * RAWF];
    const float* drow = dx + (size_t)root[r] * RAWF;
    float acc = 0.f;
    for (int k = 0; k < RAWF; k++)
        acc += (mrow[k] * inv) * Wl1[(size_t)k * 512 + c];
    for (int k = 0; k < RAWF; k++)
        acc += drow[k] * Wl1[(size_t)(RAWF + k) * 512 + c];
    acc += bl1[c];
    float a = *pa;
    g_nx1[r * 512 + c] = (acc >= 0.f) ? acc : a * acc;
}

// Layer 2: nx2[r][c] = prelu( nx1[r] . Wl2[:,c] + bl2[c] )
__global__ void k_mlp2(const float* __restrict__ Wl2, const float* __restrict__ bl2,
                       const float* __restrict__ pa) {
    int r = blockIdx.x;       // 0..127
    int c = threadIdx.x;      // 0..255
    float acc = 0.f;
    for (int k = 0; k < 512; k++)
        acc += g_nx1[r * 512 + k] * Wl2[(size_t)k * Hh + c];
    acc += bl2[c];
    float a = *pa;
    g_nx2[r * Hh + c] = (acc >= 0.f) ? acc : a * acc;
}

// ---------------- concat (divisions folded in) + classifier + log_softmax ----------
__global__ void k_cat5() {
    int g = blockIdx.x, f = threadIdx.x;
    float inv = 1.f / fmaxf((float)g_cnt[g], 1.f);
    float* o = &g_cat5[g * (5 * Hh)];
    o[f]          = g_acc0[g * Hh + f] * inv;
    o[Hh + f]     = g_acc1[g * Hh + f] * inv;
    o[2 * Hh + f] = g_acc2[g * Hh + f] * inv;
    o[3 * Hh + f] = g_nx2[g * Hh + f];
    o[4 * Hh + f] = __uint_as_float(g_maxacc[g * Hh + f]);
}

__global__ void k_final(const float* __restrict__ W5, const float* __restrict__ b5,
                        float* __restrict__ out) {
    __shared__ float sh[128];
    int r = blockIdx.x, t = threadIdx.x;
    int c = t & 3, kk = t >> 2;
    float acc = 0.f;
    for (int k = kk; k < 5 * Hh; k += 32)
        acc += g_cat5[r * (5 * Hh) + k] * W5[k * Cc + c];
    sh[t] = acc;
    __syncthreads();
    if (t < 4) {
        float s = 0.f;
        for (int q = 0; q < 32; q++) s += sh[q * 4 + t];
        s += b5[t];
        sh[t] = s;
    }
    __syncthreads();
    if (t == 0) {
        float m = sh[0];
        for (int q = 1; q < 4; q++) m = fmaxf(m, sh[q]);
        float lse = 0.f;
        for (int q = 0; q < 4; q++) lse += expf(sh[q] - m);
        lse = logf(lse);
        for (int q = 0; q < 4; q++) out[r * Cc + q] = sh[q] - m - lse;
    }
}

// ---------------- launch ----------------
extern "C" void kernel_launch(void* const* d_in, const int* in_sizes, int n_in,
                              void* d_out, int out_size) {
    const float* graph_x = (const float*)d_in[0];
    const float* data_x  = (const float*)d_in[2];
    const int*   ei      = (const int*)d_in[3];
    const int*   rei     = (const int*)d_in[4];
    const int*   batch   = (const int*)d_in[6];   // x_batch (== graph_batch)
    const int*   root    = (const int*)d_in[7];
    const float* W1  = (const float*)d_in[8];
    const float* b1  = (const float*)d_in[9];
    const float* Wc0 = (const float*)d_in[10];
    const float* bc0 = (const float*)d_in[11];
    const float* Wc1 = (const float*)d_in[12];
    const float* bc1 = (const float*)d_in[13];
    const float* Wc2 = (const float*)d_in[14];
    const float* bc2 = (const float*)d_in[15];
    const float* Wl1 = (const float*)d_in[16];
    const float* bl1 = (const float*)d_in[17];
    const float* Wl2 = (const float*)d_in[18];
    const float* bl2 = (const float*)d_in[19];
    const float* pa  = (const float*)d_in[20];
    const float* W5  = (const float*)d_in[21];
    const float* b5  = (const float*)d_in[22];
    float* out = (float*)d_out;

    // --- preprocessing ---
    k_zero<<<(Bb * RAWF + 255) / 256, 256>>>();
    k_deg<<<(Ee + 255) / 256, 256>>>(ei, rei);
    k_dinv<<<(Nn + 255) / 256, 256>>>();
    k_scan1<<<1, 1024>>>();
    k_fill1<<<(Ee + 255) / 256, 256>>>(ei);
    k_cnt_hist<<<(Nn + 255) / 256, 256>>>(batch);

    dim3 gemmGrid((Nn + 127) / 128, Hh / 128);
    int poolBlocks = (Nn + CH - 1) / CH;
    int pbZero = ((int)(((size_t)Nn * Hh + 255) / 256));

    // --- branch 1: GCN(graph_x) -> relu -> max pool (exonerated fast path) ---
    sgemm_g1<<<gemmGrid, 256>>>(graph_x, W1);
    gather1<<<Nn, 256>>>(b1);
    pacc_max<<<poolBlocks, 256>>>(batch);

    // --- branch 2: segment mean + root + naive 2-layer PReLU MLP ---
    k_msum<<<dim3(poolBlocks, (RAWF + 255) / 256), 256>>>(data_x, batch);
    k_mlp1<<<Bb, 512>>>(data_x, root, Wl1, bl1, pa);
    k_mlp2<<<Bb, 256>>>(Wl2, bl2, pa);

    // --- branch 3: 3x GCN over raw graph (scatter-atomic propagate), mean pools ---
    sgemm_dx<<<gemmGrid, 256>>>(data_x, Wc0);
    k_zeroP<<<pbZero, 256>>>();
    k_scatter<<<Ee, 256>>>(rei);
    k_selfrelu<<<Nn, 256>>>(bc0);
    pacc_mean<<<poolBlocks, 256>>>(0, batch);

    sgemm_x<<<gemmGrid, 256>>>(Wc1);
    k_zeroP<<<pbZero, 256>>>();
    k_scatter<<<Ee, 256>>>(rei);
    k_selfrelu<<<Nn, 256>>>(bc1);
    pacc_mean<<<poolBlocks, 256>>>(1, batch);

    sgemm_x<<<gemmGrid, 256>>>(Wc2);
    k_zeroP<<<pbZero, 256>>>();
    k_scatter<<<Ee, 256>>>(rei);
    k_selfrelu<<<Nn, 256>>>(bc2);
    pacc_mean<<<poolBlocks, 256>>>(2, batch);

    // --- final ---
    k_cat5<<<Bb, 256>>>();
    k_final<<<Bb, 128>>>(W5, b5, out);
}